// round 1
// baseline (speedup 1.0000x reference)
#include <cuda_runtime.h>

// ---------------- problem constants ----------------
#define Dc   1024
#define Ec   8
#define Hc   2730
#define HP   2752            // H padded to multiple of 64 (tail cols are zeros)
#define NT   8192            // tokens
#define MA   (2*NT)          // assignments (top-2)
#define TM   64
#define TN   64
#define TKc  16
#define MMAX (MA + Ec*TM)    // worst-case padded rows = 16896

// ---------------- device scratch (no allocs allowed) ----------------
__device__ int   g_cnt[Ec];
__device__ int   g_cur[Ec];
__device__ int   g_off[Ec + 1];
__device__ int   g_tok[MMAX];
__device__ float g_gate[MMAX];
__device__ int   g_topi[NT * 2];
__device__ float g_topv[NT * 2];
__device__ int   g_pos[NT * 2];
__device__ float g_h[(size_t)MMAX * HP];   // ~186 MB
__device__ float g_y[(size_t)MMAX * Dc];   // ~69 MB

// ---------------- init: reset counters / token map every replay ----------------
__global__ void k_init() {
    int i = blockIdx.x * blockDim.x + threadIdx.x;
    if (i < Ec) { g_cnt[i] = 0; g_cur[i] = 0; }
    if (i < MMAX) { g_tok[i] = -1; g_gate[i] = 0.0f; }
}

// ---------------- router: one warp per token ----------------
__global__ void k_router(const float* __restrict__ x, const float* __restrict__ Wr) {
    int warp = threadIdx.x >> 5;
    int lane = threadIdx.x & 31;
    int n = blockIdx.x * 8 + warp;
    if (n >= NT) return;
    const float* xr = x + (size_t)n * Dc;

    float acc[Ec];
#pragma unroll
    for (int e = 0; e < Ec; e++) acc[e] = 0.0f;

    for (int d0 = lane * 4; d0 < Dc; d0 += 128) {
        float4 xv = *(const float4*)(xr + d0);
        float xs[4] = {xv.x, xv.y, xv.z, xv.w};
#pragma unroll
        for (int j = 0; j < 4; j++) {
            float4 w0 = *(const float4*)(Wr + (d0 + j) * Ec);
            float4 w1 = *(const float4*)(Wr + (d0 + j) * Ec + 4);
            acc[0] += xs[j] * w0.x;  acc[1] += xs[j] * w0.y;
            acc[2] += xs[j] * w0.z;  acc[3] += xs[j] * w0.w;
            acc[4] += xs[j] * w1.x;  acc[5] += xs[j] * w1.y;
            acc[6] += xs[j] * w1.z;  acc[7] += xs[j] * w1.w;
        }
    }
#pragma unroll
    for (int e = 0; e < Ec; e++) {
#pragma unroll
        for (int o = 16; o > 0; o >>= 1)
            acc[e] += __shfl_xor_sync(0xffffffffu, acc[e], o);
    }
    if (lane == 0) {
        float mx = acc[0];
#pragma unroll
        for (int e = 1; e < Ec; e++) mx = fmaxf(mx, acc[e]);
        float p[Ec], s = 0.0f;
#pragma unroll
        for (int e = 0; e < Ec; e++) { p[e] = __expf(acc[e] - mx); s += p[e]; }
        float inv = 1.0f / s;
        int i1 = 0;
#pragma unroll
        for (int e = 1; e < Ec; e++) if (p[e] > p[i1]) i1 = e;
        int i2 = (i1 == 0) ? 1 : 0;
#pragma unroll
        for (int e = 0; e < Ec; e++) if (e != i1 && p[e] > p[i2]) i2 = e;
        g_topi[2 * n]     = i1;  g_topv[2 * n]     = p[i1] * inv;
        g_topi[2 * n + 1] = i2;  g_topv[2 * n + 1] = p[i2] * inv;
        atomicAdd(&g_cnt[i1], 1);
        atomicAdd(&g_cnt[i2], 1);
    }
}

// ---------------- scan: tile-padded per-expert offsets ----------------
__global__ void k_scan() {
    if (threadIdx.x == 0 && blockIdx.x == 0) {
        int o = 0;
        for (int e = 0; e < Ec; e++) {
            g_off[e] = o;
            o += ((g_cnt[e] + TM - 1) / TM) * TM;
        }
        g_off[Ec] = o;
    }
}

// ---------------- scatter tokens into expert segments ----------------
__global__ void k_scatter() {
    int n = blockIdx.x * blockDim.x + threadIdx.x;
    if (n >= NT) return;
#pragma unroll
    for (int k = 0; k < 2; k++) {
        int e = g_topi[2 * n + k];
        int pos = g_off[e] + atomicAdd(&g_cur[e], 1);
        g_tok[pos]  = n;
        g_gate[pos] = g_topv[2 * n + k];
        g_pos[2 * n + k] = pos;
    }
}

// ---------------- FFN1: h = silu(X@W1) * (X@W3), 64x64x16 tiles ----------------
__global__ void __launch_bounds__(256) k_ffn1(const float* __restrict__ x,
                                              const float* __restrict__ W1,
                                              const float* __restrict__ W3) {
    __shared__ float Xs[TKc][TM + 4];
    __shared__ float B1s[TKc][TN + 4];
    __shared__ float B3s[TKc][TN + 4];

    int m0 = blockIdx.y * TM;
    if (m0 >= g_off[Ec]) return;
    int e = 0;
#pragma unroll
    for (int i = 1; i < Ec; i++) if (m0 >= g_off[i]) e = i;

    int n0 = blockIdx.x * TN;
    int tid = threadIdx.x;
    int ml = tid >> 2, kl = (tid & 3) * 4;     // X-tile loader coords
    int kw = tid >> 4, nw = (tid & 15) * 4;    // W-tile loader coords
    int ty = tid >> 4, tx = tid & 15;          // compute coords

    int tok = g_tok[m0 + ml];
    const float* xp = x + (size_t)(tok < 0 ? 0 : tok) * Dc + kl;
    size_t wbase = (size_t)e * Dc * Hc + (size_t)kw * Hc + (n0 + nw);
    const float* w1p = W1 + wbase;
    const float* w3p = W3 + wbase;
    bool tail = (n0 + TN > Hc);

    float a1[4][4], a3[4][4];
#pragma unroll
    for (int i = 0; i < 4; i++)
#pragma unroll
        for (int j = 0; j < 4; j++) { a1[i][j] = 0.0f; a3[i][j] = 0.0f; }

    for (int k0 = 0; k0 < Dc; k0 += TKc) {
        float4 xv = make_float4(0.f, 0.f, 0.f, 0.f);
        if (tok >= 0) xv = *(const float4*)(xp + k0);
        Xs[kl + 0][ml] = xv.x; Xs[kl + 1][ml] = xv.y;
        Xs[kl + 2][ml] = xv.z; Xs[kl + 3][ml] = xv.w;

        const float* w1r = w1p + (size_t)k0 * Hc;
        const float* w3r = w3p + (size_t)k0 * Hc;
        if (!tail) {
            // H is even so float2 at even col is always 8B-aligned
            *(float2*)&B1s[kw][nw]     = *(const float2*)(w1r);
            *(float2*)&B1s[kw][nw + 2] = *(const float2*)(w1r + 2);
            *(float2*)&B3s[kw][nw]     = *(const float2*)(w3r);
            *(float2*)&B3s[kw][nw + 2] = *(const float2*)(w3r + 2);
        } else {
            int c = n0 + nw;
            float2 z = make_float2(0.f, 0.f);
            *(float2*)&B1s[kw][nw]     = (c     < Hc) ? *(const float2*)(w1r)     : z;
            *(float2*)&B1s[kw][nw + 2] = (c + 2 < Hc) ? *(const float2*)(w1r + 2) : z;
            *(float2*)&B3s[kw][nw]     = (c     < Hc) ? *(const float2*)(w3r)     : z;
            *(float2*)&B3s[kw][nw + 2] = (c + 2 < Hc) ? *(const float2*)(w3r + 2) : z;
        }
        __syncthreads();
#pragma unroll
        for (int kk = 0; kk < TKc; kk++) {
            float4 av  = *(const float4*)&Xs[kk][ty * 4];
            float4 b1v = *(const float4*)&B1s[kk][tx * 4];
            float4 b3v = *(const float4*)&B3s[kk][tx * 4];
            float aa[4]  = {av.x, av.y, av.z, av.w};
            float bb1[4] = {b1v.x, b1v.y, b1v.z, b1v.w};
            float bb3[4] = {b3v.x, b3v.y, b3v.z, b3v.w};
#pragma unroll
            for (int i = 0; i < 4; i++)
#pragma unroll
                for (int j = 0; j < 4; j++) {
                    a1[i][j] += aa[i] * bb1[j];
                    a3[i][j] += aa[i] * bb3[j];
                }
        }
        __syncthreads();
    }
    // epilogue: silu(a1) * a3  ->  g_h
#pragma unroll
    for (int i = 0; i < 4; i++) {
        int row = m0 + ty * 4 + i;
        float4 hv;
        float* o = (float*)&hv;
#pragma unroll
        for (int j = 0; j < 4; j++) {
            float v = a1[i][j];
            float s = v / (1.0f + __expf(-v));
            o[j] = s * a3[i][j];
        }
        *(float4*)&g_h[(size_t)row * HP + n0 + tx * 4] = hv;
    }
}

// ---------------- FFN2: y = gate * (h @ W2) ----------------
__global__ void __launch_bounds__(256) k_ffn2(const float* __restrict__ W2) {
    __shared__ float As[TKc][TM + 4];
    __shared__ float Bs[TKc][TN + 4];

    int m0 = blockIdx.y * TM;
    if (m0 >= g_off[Ec]) return;
    int e = 0;
#pragma unroll
    for (int i = 1; i < Ec; i++) if (m0 >= g_off[i]) e = i;

    int n0 = blockIdx.x * TN;
    int tid = threadIdx.x;
    int ml = tid >> 2, kl = (tid & 3) * 4;
    int kw = tid >> 4, nw = (tid & 15) * 4;
    int ty = tid >> 4, tx = tid & 15;

    const float* ap = g_h + (size_t)(m0 + ml) * HP + kl;
    const float* bp = W2 + (size_t)e * Hc * Dc + (size_t)kw * Dc + (n0 + nw);

    float acc[4][4];
#pragma unroll
    for (int i = 0; i < 4; i++)
#pragma unroll
        for (int j = 0; j < 4; j++) acc[i][j] = 0.0f;

    for (int k0 = 0; k0 < HP; k0 += TKc) {
        float4 av = *(const float4*)(ap + k0);
        As[kl + 0][ml] = av.x; As[kl + 1][ml] = av.y;
        As[kl + 2][ml] = av.z; As[kl + 3][ml] = av.w;

        int kr = k0 + kw;                       // padded K rows beyond Hc: A is 0, skip B
        float4 bv = make_float4(0.f, 0.f, 0.f, 0.f);
        if (kr < Hc) bv = *(const float4*)(bp + (size_t)k0 * Dc);
        *(float4*)&Bs[kw][nw] = bv;
        __syncthreads();
#pragma unroll
        for (int kk = 0; kk < TKc; kk++) {
            float4 av2 = *(const float4*)&As[kk][ty * 4];
            float4 bv2 = *(const float4*)&Bs[kk][tx * 4];
            float aa[4] = {av2.x, av2.y, av2.z, av2.w};
            float bb[4] = {bv2.x, bv2.y, bv2.z, bv2.w};
#pragma unroll
            for (int i = 0; i < 4; i++)
#pragma unroll
                for (int j = 0; j < 4; j++) acc[i][j] += aa[i] * bb[j];
        }
        __syncthreads();
    }
#pragma unroll
    for (int i = 0; i < 4; i++) {
        int row = m0 + ty * 4 + i;
        float g = g_gate[row];
        float4 yv;
        yv.x = g * acc[i][0]; yv.y = g * acc[i][1];
        yv.z = g * acc[i][2]; yv.w = g * acc[i][3];
        *(float4*)&g_y[(size_t)row * Dc + n0 + tx * 4] = yv;
    }
}

// ---------------- combine: out[n] = y[pos0] + y[pos1] ----------------
__global__ void k_combine(float* __restrict__ out) {
    int i = blockIdx.x * blockDim.x + threadIdx.x;   // over NT * (Dc/4)
    int n = i >> 8;              // Dc/4 = 256
    int c = (i & 255) * 4;
    int p0 = g_pos[2 * n], p1 = g_pos[2 * n + 1];
    float4 a = *(const float4*)&g_y[(size_t)p0 * Dc + c];
    float4 b = *(const float4*)&g_y[(size_t)p1 * Dc + c];
    float4 o;
    o.x = a.x + b.x; o.y = a.y + b.y; o.z = a.z + b.z; o.w = a.w + b.w;
    *(float4*)(out + (size_t)n * Dc + c) = o;
}

// ---------------- launch ----------------
extern "C" void kernel_launch(void* const* d_in, const int* in_sizes, int n_in,
                              void* d_out, int out_size) {
    const float* x  = (const float*)d_in[0];
    const float* Wr = (const float*)d_in[1];
    const float* W1 = (const float*)d_in[2];
    const float* W2 = (const float*)d_in[3];
    const float* W3 = (const float*)d_in[4];
    float* out = (float*)d_out;

    k_init<<<(MMAX + 255) / 256, 256>>>();
    k_router<<<NT / 8, 256>>>(x, Wr);
    k_scan<<<1, 32>>>();
    k_scatter<<<NT / 256, 256>>>();

    dim3 g1(HP / TN, MMAX / TM);   // (43, 264)
    k_ffn1<<<g1, 256>>>(x, W1, W3);

    dim3 g2(Dc / TN, MMAX / TM);   // (16, 264)
    k_ffn2<<<g2, 256>>>(W2);

    k_combine<<<(NT * (Dc / 4)) / 256, 256>>>(out);
}

// round 3
// speedup vs baseline: 2.8877x; 2.8877x over previous
#include <cuda_runtime.h>
#include <cstdint>

// ---------------- problem constants ----------------
#define Dc   1024
#define Ec   8
#define Hc   2730
#define HP2  2816            // H padded to 22*128
#define NT   8192
#define TMp  128             // per-expert row padding
#define MMAX (2*NT + Ec*TMp) // 17408
#define KC   32              // K per pipeline chunk
#define SAF  36              // smem row stride in floats (conflict-free for frag LDS)

// ---------------- device scratch ----------------
__device__ int   g_cnt[Ec];
__device__ int   g_cur[Ec];
__device__ int   g_off[Ec + 1];
__device__ int   g_tok[MMAX];
__device__ float g_gate[MMAX];
__device__ int   g_topi[NT * 2];
__device__ float g_topv[NT * 2];
__device__ int   g_pos[NT * 2];
__device__ float g_w1t[(size_t)Ec * HP2 * Dc];   // W1^T tf32-rounded [E][HP2][Dc]
__device__ float g_w3t[(size_t)Ec * HP2 * Dc];   // W3^T
__device__ float g_w2t[(size_t)Ec * Dc * HP2];   // W2^T [E][Dc][HP2]
__device__ float g_h[(size_t)MMAX * HP2];
__device__ float g_y[(size_t)MMAX * Dc];

// ---------------- helpers ----------------
__device__ __forceinline__ uint32_t smem_u32(const void* p) {
    uint32_t a;
    asm("{ .reg .u64 t; cvta.to.shared.u64 t, %1; cvt.u32.u64 %0, t; }" : "=r"(a) : "l"(p));
    return a;
}
__device__ __forceinline__ float rtf32(float v) {
    uint32_t u;
    asm("cvt.rna.tf32.f32 %0, %1;" : "=r"(u) : "f"(v));
    return __uint_as_float(u);
}
#define CP16(dst, src) asm volatile("cp.async.cg.shared.global [%0], [%1], 16;" :: "r"(dst), "l"(src) : "memory")
#define CP_COMMIT()    asm volatile("cp.async.commit_group;" ::: "memory")
#define CP_WAIT0()     asm volatile("cp.async.wait_group 0;" ::: "memory")

// tf32 m16n8k8 mma: D(16x8,f32) += A(16x8,tf32,row) * B(8x8,tf32,col)
__device__ __forceinline__ void mma8(float* d, const uint32_t* a, const uint32_t* b) {
    asm volatile(
        "mma.sync.aligned.m16n8k8.row.col.f32.tf32.tf32.f32 "
        "{%0,%1,%2,%3}, {%4,%5,%6,%7}, {%8,%9}, {%0,%1,%2,%3};"
        : "+f"(d[0]), "+f"(d[1]), "+f"(d[2]), "+f"(d[3])
        : "r"(a[0]), "r"(a[1]), "r"(a[2]), "r"(a[3]), "r"(b[0]), "r"(b[1]));
}

// ---------------- init ----------------
__global__ void k_init() {
    int i = blockIdx.x * blockDim.x + threadIdx.x;
    if (i < Ec) { g_cnt[i] = 0; g_cur[i] = 0; }
    if (i < MMAX) { g_tok[i] = -1; g_gate[i] = 0.0f; }
}

// ---------------- transpose (+ tf32 round, + zero pad) ----------------
// in [E][R][C] -> out [E][Cpad][Rpad]
__global__ void k_transpose(const float* __restrict__ in, float* __restrict__ out,
                            int R, int C, int Rpad, int Cpad) {
    __shared__ float ts[32][33];
    int e = blockIdx.z;
    const float* ip = in + (size_t)e * R * C;
    float* op = out + (size_t)e * Cpad * Rpad;
    int c0 = blockIdx.x * 32, r0 = blockIdx.y * 32;
#pragma unroll
    for (int i = 0; i < 32; i += 8) {
        int r = r0 + threadIdx.y + i;
        float v = 0.0f;
        if (r < R && c0 + threadIdx.x < C) v = ip[(size_t)r * C + c0 + threadIdx.x];
        ts[threadIdx.y + i][threadIdx.x] = v;
    }
    __syncthreads();
#pragma unroll
    for (int i = 0; i < 32; i += 8) {
        int cc = c0 + threadIdx.y + i;
        int rr = r0 + threadIdx.x;
        if (cc < Cpad && rr < Rpad)
            op[(size_t)cc * Rpad + rr] = rtf32(ts[threadIdx.x][threadIdx.y + i]);
    }
}

// ---------------- router ----------------
__global__ void k_router(const float* __restrict__ x, const float* __restrict__ Wr) {
    int warp = threadIdx.x >> 5, lane = threadIdx.x & 31;
    int n = blockIdx.x * 8 + warp;
    if (n >= NT) return;
    const float* xr = x + (size_t)n * Dc;
    float acc[Ec];
#pragma unroll
    for (int e = 0; e < Ec; e++) acc[e] = 0.0f;
    for (int d0 = lane * 4; d0 < Dc; d0 += 128) {
        float4 xv = *(const float4*)(xr + d0);
        float xs[4] = {xv.x, xv.y, xv.z, xv.w};
#pragma unroll
        for (int j = 0; j < 4; j++) {
            float4 w0 = *(const float4*)(Wr + (d0 + j) * Ec);
            float4 w1 = *(const float4*)(Wr + (d0 + j) * Ec + 4);
            acc[0] += xs[j] * w0.x; acc[1] += xs[j] * w0.y;
            acc[2] += xs[j] * w0.z; acc[3] += xs[j] * w0.w;
            acc[4] += xs[j] * w1.x; acc[5] += xs[j] * w1.y;
            acc[6] += xs[j] * w1.z; acc[7] += xs[j] * w1.w;
        }
    }
#pragma unroll
    for (int e = 0; e < Ec; e++)
#pragma unroll
        for (int o = 16; o > 0; o >>= 1)
            acc[e] += __shfl_xor_sync(0xffffffffu, acc[e], o);
    if (lane == 0) {
        float mx = acc[0];
#pragma unroll
        for (int e = 1; e < Ec; e++) mx = fmaxf(mx, acc[e]);
        float p[Ec], s = 0.0f;
#pragma unroll
        for (int e = 0; e < Ec; e++) { p[e] = __expf(acc[e] - mx); s += p[e]; }
        float inv = 1.0f / s;
        int i1 = 0;
#pragma unroll
        for (int e = 1; e < Ec; e++) if (p[e] > p[i1]) i1 = e;
        int i2 = (i1 == 0) ? 1 : 0;
#pragma unroll
        for (int e = 0; e < Ec; e++) if (e != i1 && p[e] > p[i2]) i2 = e;
        g_topi[2 * n] = i1;     g_topv[2 * n] = p[i1] * inv;
        g_topi[2 * n + 1] = i2; g_topv[2 * n + 1] = p[i2] * inv;
        atomicAdd(&g_cnt[i1], 1);
        atomicAdd(&g_cnt[i2], 1);
    }
}

__global__ void k_scan() {
    if (threadIdx.x == 0 && blockIdx.x == 0) {
        int o = 0;
        for (int e = 0; e < Ec; e++) {
            g_off[e] = o;
            o += ((g_cnt[e] + TMp - 1) / TMp) * TMp;
        }
        g_off[Ec] = o;
    }
}

__global__ void k_scatter() {
    int n = blockIdx.x * blockDim.x + threadIdx.x;
    if (n >= NT) return;
#pragma unroll
    for (int k = 0; k < 2; k++) {
        int e = g_topi[2 * n + k];
        int pos = g_off[e] + atomicAdd(&g_cur[e], 1);
        g_tok[pos] = n;
        g_gate[pos] = g_topv[2 * n + k];
        g_pos[2 * n + k] = pos;
    }
}

// ============ FFN1: h = silu(X@W1t) * (X@W3t), 128x128 tiles, mma.sync tf32 ============
// smem per stage (floats): A 128*SAF, B1 128*SAF, B3 128*SAF
#define F1_AOFF   0
#define F1_B1OFF  (128 * SAF)
#define F1_B3OFF  (256 * SAF)
#define F1_STG    (384 * SAF)          // floats per stage
#define F1_SMEM   (2 * F1_STG * 4)     // bytes

__global__ void __launch_bounds__(256, 1) k_ffn1(const float* __restrict__ x) {
    extern __shared__ float sm[];
    int m0 = blockIdx.y * 128;
    if (m0 >= g_off[Ec]) return;
    int e = 0;
#pragma unroll
    for (int i = 1; i < Ec; i++) if (m0 >= g_off[i]) e = i;
    int n0 = blockIdx.x * 128;

    int tid = threadIdx.x, wid = tid >> 5, lane = tid & 31;
    int wm = wid & 3, wn = wid >> 1 & 0 /*dummy*/;
    wn = wid >> 2;
    int gi = lane >> 2, ti = lane & 3;

    // loader coords: rows r0, r0+64; cols c8..c8+7
    int r0 = tid >> 2;
    int c8 = (tid & 3) * 8;

    int t0 = g_tok[m0 + r0], t1 = g_tok[m0 + r0 + 64];
    const float* xa0 = x + (size_t)(t0 < 0 ? 0 : t0) * Dc + c8;
    const float* xa1 = x + (size_t)(t1 < 0 ? 0 : t1) * Dc + c8;

    size_t bb = ((size_t)e * HP2 + n0 + r0) * Dc + c8;
    const float* b1p0 = g_w1t + bb;
    const float* b1p1 = b1p0 + (size_t)64 * Dc;
    const float* b3p0 = g_w3t + bb;
    const float* b3p1 = b3p0 + (size_t)64 * Dc;

    uint32_t smb = smem_u32(sm);
    // cp.async dst addrs (bytes) for both stages
    uint32_t dstB1 = smb + (F1_B1OFF + r0 * SAF + c8) * 4;
    uint32_t dstB3 = smb + (F1_B3OFF + r0 * SAF + c8) * 4;
    const uint32_t rowB = 64 * SAF * 4;     // +64 rows
    float* sAst = sm + (r0 * SAF + c8);     // A store base (stage 0)

    float acc1[2][8][4], acc3[2][8][4];
#pragma unroll
    for (int mt = 0; mt < 2; mt++)
#pragma unroll
        for (int nt = 0; nt < 8; nt++)
#pragma unroll
            for (int j = 0; j < 4; j++) { acc1[mt][nt][j] = 0.f; acc3[mt][nt][j] = 0.f; }

    const int nc = Dc / KC;   // 32

    // ---- prologue: chunk 0 -> stage 0 ----
    {
        float4 a00 = make_float4(0,0,0,0), a01 = a00, a10 = a00, a11 = a00;
        if (t0 >= 0) { a00 = *(const float4*)(xa0); a01 = *(const float4*)(xa0 + 4); }
        if (t1 >= 0) { a10 = *(const float4*)(xa1); a11 = *(const float4*)(xa1 + 4); }
        CP16(dstB1,            b1p0); CP16(dstB1 + 16,        b1p0 + 4);
        CP16(dstB1 + rowB,     b1p1); CP16(dstB1 + rowB + 16, b1p1 + 4);
        CP16(dstB3,            b3p0); CP16(dstB3 + 16,        b3p0 + 4);
        CP16(dstB3 + rowB,     b3p1); CP16(dstB3 + rowB + 16, b3p1 + 4);
        CP_COMMIT();
        float* s0 = sAst;
        s0[0] = rtf32(a00.x); s0[1] = rtf32(a00.y); s0[2] = rtf32(a00.z); s0[3] = rtf32(a00.w);
        s0[4] = rtf32(a01.x); s0[5] = rtf32(a01.y); s0[6] = rtf32(a01.z); s0[7] = rtf32(a01.w);
        float* s1 = s0 + 64 * SAF;
        s1[0] = rtf32(a10.x); s1[1] = rtf32(a10.y); s1[2] = rtf32(a10.z); s1[3] = rtf32(a10.w);
        s1[4] = rtf32(a11.x); s1[5] = rtf32(a11.y); s1[6] = rtf32(a11.z); s1[7] = rtf32(a11.w);
        CP_WAIT0();
        __syncthreads();
    }

    for (int c = 0; c < nc; ++c) {
        int cur = c & 1, nxt = cur ^ 1;
        bool pf = (c + 1 < nc);
        float4 a00, a01, a10, a11;
        if (pf) {
            int k0 = (c + 1) * KC;
            a00 = make_float4(0,0,0,0); a01 = a00; a10 = a00; a11 = a00;
            if (t0 >= 0) { a00 = *(const float4*)(xa0 + k0); a01 = *(const float4*)(xa0 + k0 + 4); }
            if (t1 >= 0) { a10 = *(const float4*)(xa1 + k0); a11 = *(const float4*)(xa1 + k0 + 4); }
            uint32_t so = nxt * (uint32_t)(F1_STG * 4);
            CP16(dstB1 + so,            b1p0 + k0); CP16(dstB1 + so + 16,        b1p0 + k0 + 4);
            CP16(dstB1 + so + rowB,     b1p1 + k0); CP16(dstB1 + so + rowB + 16, b1p1 + k0 + 4);
            CP16(dstB3 + so,            b3p0 + k0); CP16(dstB3 + so + 16,        b3p0 + k0 + 4);
            CP16(dstB3 + so + rowB,     b3p1 + k0); CP16(dstB3 + so + rowB + 16, b3p1 + k0 + 4);
            CP_COMMIT();
        }
        // ---- compute chunk c from stage cur ----
        {
            const float* sA  = sm + cur * F1_STG + F1_AOFF;
            const float* sB1 = sm + cur * F1_STG + F1_B1OFF;
            const float* sB3 = sm + cur * F1_STG + F1_B3OFF;
#pragma unroll
            for (int ks = 0; ks < 4; ks++) {
                int kb = ks * 8;
                uint32_t af[2][4];
#pragma unroll
                for (int mt = 0; mt < 2; mt++) {
                    int rb = wm * 32 + mt * 16;
                    af[mt][0] = __float_as_uint(sA[(rb + gi) * SAF + kb + ti]);
                    af[mt][1] = __float_as_uint(sA[(rb + gi + 8) * SAF + kb + ti]);
                    af[mt][2] = __float_as_uint(sA[(rb + gi) * SAF + kb + ti + 4]);
                    af[mt][3] = __float_as_uint(sA[(rb + gi + 8) * SAF + kb + ti + 4]);
                }
#pragma unroll
                for (int nt = 0; nt < 8; nt++) {
                    int nb = (wn * 64 + nt * 8 + gi) * SAF + kb + ti;
                    uint32_t bf1[2] = {__float_as_uint(sB1[nb]), __float_as_uint(sB1[nb + 4])};
                    uint32_t bf3[2] = {__float_as_uint(sB3[nb]), __float_as_uint(sB3[nb + 4])};
                    mma8(acc1[0][nt], af[0], bf1);
                    mma8(acc1[1][nt], af[1], bf1);
                    mma8(acc3[0][nt], af[0], bf3);
                    mma8(acc3[1][nt], af[1], bf3);
                }
            }
        }
        if (pf) {
            float* s0 = sAst + nxt * F1_STG;
            s0[0] = rtf32(a00.x); s0[1] = rtf32(a00.y); s0[2] = rtf32(a00.z); s0[3] = rtf32(a00.w);
            s0[4] = rtf32(a01.x); s0[5] = rtf32(a01.y); s0[6] = rtf32(a01.z); s0[7] = rtf32(a01.w);
            float* s1 = s0 + 64 * SAF;
            s1[0] = rtf32(a10.x); s1[1] = rtf32(a10.y); s1[2] = rtf32(a10.z); s1[3] = rtf32(a10.w);
            s1[4] = rtf32(a11.x); s1[5] = rtf32(a11.y); s1[6] = rtf32(a11.z); s1[7] = rtf32(a11.w);
        }
        CP_WAIT0();
        __syncthreads();
    }

    // ---- epilogue: silu(d1)*d3 -> g_h ----
#pragma unroll
    for (int mt = 0; mt < 2; mt++) {
#pragma unroll
        for (int nt = 0; nt < 8; nt++) {
            int row = m0 + wm * 32 + mt * 16 + gi;
            int col = n0 + wn * 64 + nt * 8 + 2 * ti;
            const float* d1 = acc1[mt][nt];
            const float* d3 = acc3[mt][nt];
            float2 o0, o1;
            o0.x = rtf32(d1[0] / (1.0f + __expf(-d1[0])) * d3[0]);
            o0.y = rtf32(d1[1] / (1.0f + __expf(-d1[1])) * d3[1]);
            o1.x = rtf32(d1[2] / (1.0f + __expf(-d1[2])) * d3[2]);
            o1.y = rtf32(d1[3] / (1.0f + __expf(-d1[3])) * d3[3]);
            *(float2*)(g_h + (size_t)row * HP2 + col) = o0;
            *(float2*)(g_h + (size_t)(row + 8) * HP2 + col) = o1;
        }
    }
}

// ============ FFN2: y = gate * (h @ W2t), 128x128 tiles ============
#define F2_AOFF  0
#define F2_BOFF  (128 * SAF)
#define F2_STG   (256 * SAF)
#define F2_SMEM  (2 * F2_STG * 4)

__global__ void __launch_bounds__(256, 1) k_ffn2() {
    extern __shared__ float sm[];
    int m0 = blockIdx.y * 128;
    if (m0 >= g_off[Ec]) return;
    int e = 0;
#pragma unroll
    for (int i = 1; i < Ec; i++) if (m0 >= g_off[i]) e = i;
    int n0 = blockIdx.x * 128;

    int tid = threadIdx.x, wid = tid >> 5, lane = tid & 31;
    int wm = wid & 3, wn = wid >> 2;
    int gi = lane >> 2, ti = lane & 3;

    int r0 = tid >> 2;
    int c8 = (tid & 3) * 8;

    const float* ap0 = g_h + (size_t)(m0 + r0) * HP2 + c8;
    const float* ap1 = ap0 + (size_t)64 * HP2;
    size_t bb = ((size_t)e * Dc + n0 + r0) * HP2 + c8;
    const float* bp0 = g_w2t + bb;
    const float* bp1 = bp0 + (size_t)64 * HP2;

    uint32_t smb = smem_u32(sm);
    uint32_t dstA = smb + (F2_AOFF + r0 * SAF + c8) * 4;
    uint32_t dstB = smb + (F2_BOFF + r0 * SAF + c8) * 4;
    const uint32_t rowB = 64 * SAF * 4;

    float acc[2][8][4];
#pragma unroll
    for (int mt = 0; mt < 2; mt++)
#pragma unroll
        for (int nt = 0; nt < 8; nt++)
#pragma unroll
            for (int j = 0; j < 4; j++) acc[mt][nt][j] = 0.f;

    const int nc = HP2 / KC;   // 88

    // prologue
    CP16(dstA,            ap0); CP16(dstA + 16,        ap0 + 4);
    CP16(dstA + rowB,     ap1); CP16(dstA + rowB + 16, ap1 + 4);
    CP16(dstB,            bp0); CP16(dstB + 16,        bp0 + 4);
    CP16(dstB + rowB,     bp1); CP16(dstB + rowB + 16, bp1 + 4);
    CP_COMMIT();
    CP_WAIT0();
    __syncthreads();

    for (int c = 0; c < nc; ++c) {
        int cur = c & 1, nxt = cur ^ 1;
        if (c + 1 < nc) {
            int k0 = (c + 1) * KC;
            uint32_t so = nxt * (uint32_t)(F2_STG * 4);
            CP16(dstA + so,            ap0 + k0); CP16(dstA + so + 16,        ap0 + k0 + 4);
            CP16(dstA + so + rowB,     ap1 + k0); CP16(dstA + so + rowB + 16, ap1 + k0 + 4);
            CP16(dstB + so,            bp0 + k0); CP16(dstB + so + 16,        bp0 + k0 + 4);
            CP16(dstB + so + rowB,     bp1 + k0); CP16(dstB + so + rowB + 16, bp1 + k0 + 4);
            CP_COMMIT();
        }
        const float* sA = sm + cur * F2_STG + F2_AOFF;
        const float* sB = sm + cur * F2_STG + F2_BOFF;
#pragma unroll
        for (int ks = 0; ks < 4; ks++) {
            int kb = ks * 8;
            uint32_t af[2][4];
#pragma unroll
            for (int mt = 0; mt < 2; mt++) {
                int rb = wm * 32 + mt * 16;
                af[mt][0] = __float_as_uint(sA[(rb + gi) * SAF + kb + ti]);
                af[mt][1] = __float_as_uint(sA[(rb + gi + 8) * SAF + kb + ti]);
                af[mt][2] = __float_as_uint(sA[(rb + gi) * SAF + kb + ti + 4]);
                af[mt][3] = __float_as_uint(sA[(rb + gi + 8) * SAF + kb + ti + 4]);
            }
#pragma unroll
            for (int nt = 0; nt < 8; nt++) {
                int nb = (wn * 64 + nt * 8 + gi) * SAF + kb + ti;
                uint32_t bf[2] = {__float_as_uint(sB[nb]), __float_as_uint(sB[nb + 4])};
                mma8(acc[0][nt], af[0], bf);
                mma8(acc[1][nt], af[1], bf);
            }
        }
        CP_WAIT0();
        __syncthreads();
    }

    // epilogue: gate multiply -> g_y
#pragma unroll
    for (int mt = 0; mt < 2; mt++) {
        int row = m0 + wm * 32 + mt * 16 + gi;
        float ga = g_gate[row];
        float gb = g_gate[row + 8];
#pragma unroll
        for (int nt = 0; nt < 8; nt++) {
            int col = n0 + wn * 64 + nt * 8 + 2 * ti;
            const float* d = acc[mt][nt];
            float2 o0, o1;
            o0.x = ga * d[0]; o0.y = ga * d[1];
            o1.x = gb * d[2]; o1.y = gb * d[3];
            *(float2*)(g_y + (size_t)row * Dc + col) = o0;
            *(float2*)(g_y + (size_t)(row + 8) * Dc + col) = o1;
        }
    }
}

// ---------------- combine ----------------
__global__ void k_combine(float* __restrict__ out) {
    int i = blockIdx.x * blockDim.x + threadIdx.x;
    int n = i >> 8;
    int c = (i & 255) * 4;
    int p0 = g_pos[2 * n], p1 = g_pos[2 * n + 1];
    float4 a = *(const float4*)&g_y[(size_t)p0 * Dc + c];
    float4 b = *(const float4*)&g_y[(size_t)p1 * Dc + c];
    float4 o;
    o.x = a.x + b.x; o.y = a.y + b.y; o.z = a.z + b.z; o.w = a.w + b.w;
    *(float4*)(out + (size_t)n * Dc + c) = o;
}

// ---------------- launch ----------------
extern "C" void kernel_launch(void* const* d_in, const int* in_sizes, int n_in,
                              void* d_out, int out_size) {
    const float* x  = (const float*)d_in[0];
    const float* Wr = (const float*)d_in[1];
    const float* W1 = (const float*)d_in[2];
    const float* W2 = (const float*)d_in[3];
    const float* W3 = (const float*)d_in[4];
    float* out = (float*)d_out;

    float* w1t; cudaGetSymbolAddress((void**)&w1t, g_w1t);
    float* w3t; cudaGetSymbolAddress((void**)&w3t, g_w3t);
    float* w2t; cudaGetSymbolAddress((void**)&w2t, g_w2t);

    cudaFuncSetAttribute(k_ffn1, cudaFuncAttributeMaxDynamicSharedMemorySize, F1_SMEM);
    cudaFuncSetAttribute(k_ffn2, cudaFuncAttributeMaxDynamicSharedMemorySize, F2_SMEM);

    k_init<<<(MMAX + 255) / 256, 256>>>();

    dim3 tb(32, 8);
    // W1,W3: [E][Dc][Hc] -> [E][HP2][Dc]
    k_transpose<<<dim3(HP2 / 32, Dc / 32, Ec), tb>>>(W1, w1t, Dc, Hc, Dc, HP2);
    k_transpose<<<dim3(HP2 / 32, Dc / 32, Ec), tb>>>(W3, w3t, Dc, Hc, Dc, HP2);
    // W2: [E][Hc][Dc] -> [E][Dc][HP2]
    k_transpose<<<dim3(Dc / 32, HP2 / 32, Ec), tb>>>(W2, w2t, Hc, Dc, HP2, Dc);

    k_router<<<NT / 8, 256>>>(x, Wr);
    k_scan<<<1, 32>>>();
    k_scatter<<<NT / 256, 256>>>();

    k_ffn1<<<dim3(HP2 / 128, MMAX / 128), 256, F1_SMEM>>>(x);
    k_ffn2<<<dim3(Dc / 128, MMAX / 128), 256, F2_SMEM>>>();

    k_combine<<<(NT * (Dc / 4)) / 256, 256>>>(out);
}

// round 4
// speedup vs baseline: 3.8991x; 1.3503x over previous
#include <cuda_runtime.h>
#include <cuda_fp16.h>
#include <cstdint>

// ---------------- problem constants ----------------
#define Dc   1024
#define Ec   8
#define Hc   2730
#define HP2  2816            // H padded to 22*128
#define NT   8192
#define TMp  128             // per-expert row padding
#define MMAX (2*NT + Ec*TMp) // 17408
#define KC   32              // K halves per pipeline chunk (2 x k16)
#define SAH  40              // smem row stride in halves (conflict-free frag LDS)

// ---------------- device scratch ----------------
__device__ int    g_cnt[Ec];
__device__ int    g_cur[Ec];
__device__ int    g_off[Ec + 1];
__device__ int    g_tok[MMAX];
__device__ float  g_gate[MMAX];
__device__ int    g_topi[NT * 2];
__device__ float  g_topv[NT * 2];
__device__ int    g_pos[NT * 2];
__device__ __half g_w1t[(size_t)Ec * HP2 * Dc];   // W1^T fp16 [E][HP2][Dc]
__device__ __half g_w3t[(size_t)Ec * HP2 * Dc];   // W3^T
__device__ __half g_w2t[(size_t)Ec * Dc * HP2];   // W2^T [E][Dc][HP2]
__device__ __half g_h[(size_t)MMAX * HP2];        // fp16 activations
__device__ float  g_y[(size_t)MMAX * Dc];

// ---------------- helpers ----------------
__device__ __forceinline__ uint32_t smem_u32(const void* p) {
    uint32_t a;
    asm("{ .reg .u64 t; cvta.to.shared.u64 t, %1; cvt.u32.u64 %0, t; }" : "=r"(a) : "l"(p));
    return a;
}
#define CP16(dst, src) asm volatile("cp.async.cg.shared.global [%0], [%1], 16;" :: "r"(dst), "l"(src) : "memory")
#define CP_COMMIT()    asm volatile("cp.async.commit_group;" ::: "memory")
#define CP_WAIT0()     asm volatile("cp.async.wait_group 0;" ::: "memory")

// fp16 m16n8k16 mma: D(16x8,f32) += A(16x16,f16,row) * B(16x8,f16,col)
__device__ __forceinline__ void mma16(float* d, const uint32_t* a, const uint32_t* b) {
    asm volatile(
        "mma.sync.aligned.m16n8k16.row.col.f32.f16.f16.f32 "
        "{%0,%1,%2,%3}, {%4,%5,%6,%7}, {%8,%9}, {%0,%1,%2,%3};"
        : "+f"(d[0]), "+f"(d[1]), "+f"(d[2]), "+f"(d[3])
        : "r"(a[0]), "r"(a[1]), "r"(a[2]), "r"(a[3]), "r"(b[0]), "r"(b[1]));
}
#define U32S(p, idx) (*(const uint32_t*)((p) + (idx)))

// ---------------- init ----------------
__global__ void k_init() {
    int i = blockIdx.x * blockDim.x + threadIdx.x;
    if (i < Ec) { g_cnt[i] = 0; g_cur[i] = 0; }
    if (i < MMAX) { g_tok[i] = -1; g_gate[i] = 0.0f; }
}

// ---------------- transpose (+ fp16 convert, + zero pad) ----------------
// in [E][R][C] fp32 -> out [E][Cpad][Rpad] fp16
__global__ void k_transpose(const float* __restrict__ in, __half* __restrict__ out,
                            int R, int C, int Rpad, int Cpad) {
    __shared__ float ts[32][33];
    int e = blockIdx.z;
    const float* ip = in + (size_t)e * R * C;
    __half* op = out + (size_t)e * Cpad * Rpad;
    int c0 = blockIdx.x * 32, r0 = blockIdx.y * 32;
#pragma unroll
    for (int i = 0; i < 32; i += 8) {
        int r = r0 + threadIdx.y + i;
        float v = 0.0f;
        if (r < R && c0 + threadIdx.x < C) v = ip[(size_t)r * C + c0 + threadIdx.x];
        ts[threadIdx.y + i][threadIdx.x] = v;
    }
    __syncthreads();
#pragma unroll
    for (int i = 0; i < 32; i += 8) {
        int cc = c0 + threadIdx.y + i;
        int rr = r0 + threadIdx.x;
        if (cc < Cpad && rr < Rpad)
            op[(size_t)cc * Rpad + rr] = __float2half_rn(ts[threadIdx.x][threadIdx.y + i]);
    }
}

// ---------------- router ----------------
__global__ void k_router(const float* __restrict__ x, const float* __restrict__ Wr) {
    int warp = threadIdx.x >> 5, lane = threadIdx.x & 31;
    int n = blockIdx.x * 8 + warp;
    if (n >= NT) return;
    const float* xr = x + (size_t)n * Dc;
    float acc[Ec];
#pragma unroll
    for (int e = 0; e < Ec; e++) acc[e] = 0.0f;
    for (int d0 = lane * 4; d0 < Dc; d0 += 128) {
        float4 xv = *(const float4*)(xr + d0);
        float xs[4] = {xv.x, xv.y, xv.z, xv.w};
#pragma unroll
        for (int j = 0; j < 4; j++) {
            float4 w0 = *(const float4*)(Wr + (d0 + j) * Ec);
            float4 w1 = *(const float4*)(Wr + (d0 + j) * Ec + 4);
            acc[0] += xs[j] * w0.x; acc[1] += xs[j] * w0.y;
            acc[2] += xs[j] * w0.z; acc[3] += xs[j] * w0.w;
            acc[4] += xs[j] * w1.x; acc[5] += xs[j] * w1.y;
            acc[6] += xs[j] * w1.z; acc[7] += xs[j] * w1.w;
        }
    }
#pragma unroll
    for (int e = 0; e < Ec; e++)
#pragma unroll
        for (int o = 16; o > 0; o >>= 1)
            acc[e] += __shfl_xor_sync(0xffffffffu, acc[e], o);
    if (lane == 0) {
        float mx = acc[0];
#pragma unroll
        for (int e = 1; e < Ec; e++) mx = fmaxf(mx, acc[e]);
        float p[Ec], s = 0.0f;
#pragma unroll
        for (int e = 0; e < Ec; e++) { p[e] = __expf(acc[e] - mx); s += p[e]; }
        float inv = 1.0f / s;
        int i1 = 0;
#pragma unroll
        for (int e = 1; e < Ec; e++) if (p[e] > p[i1]) i1 = e;
        int i2 = (i1 == 0) ? 1 : 0;
#pragma unroll
        for (int e = 0; e < Ec; e++) if (e != i1 && p[e] > p[i2]) i2 = e;
        g_topi[2 * n] = i1;     g_topv[2 * n] = p[i1] * inv;
        g_topi[2 * n + 1] = i2; g_topv[2 * n + 1] = p[i2] * inv;
        atomicAdd(&g_cnt[i1], 1);
        atomicAdd(&g_cnt[i2], 1);
    }
}

__global__ void k_scan() {
    if (threadIdx.x == 0 && blockIdx.x == 0) {
        int o = 0;
        for (int e = 0; e < Ec; e++) {
            g_off[e] = o;
            o += ((g_cnt[e] + TMp - 1) / TMp) * TMp;
        }
        g_off[Ec] = o;
    }
}

__global__ void k_scatter() {
    int n = blockIdx.x * blockDim.x + threadIdx.x;
    if (n >= NT) return;
#pragma unroll
    for (int k = 0; k < 2; k++) {
        int e = g_topi[2 * n + k];
        int pos = g_off[e] + atomicAdd(&g_cur[e], 1);
        g_tok[pos] = n;
        g_gate[pos] = g_topv[2 * n + k];
        g_pos[2 * n + k] = pos;
    }
}

// ============ FFN1: h = silu(X@W1t) * (X@W3t), 128x128 tiles, fp16 mma ============
// smem per stage (halves): A 128*SAH, B1 128*SAH, B3 128*SAH
#define F1_A     0
#define F1_B1    (128 * SAH)
#define F1_B3    (256 * SAH)
#define F1_STGH  (384 * SAH)           // halves per stage
#define F1_SMEM  (2 * F1_STGH * 2)     // bytes = 61440

__global__ void __launch_bounds__(256, 1) k_ffn1(const float* __restrict__ x) {
    extern __shared__ __half sm[];
    int m0 = blockIdx.y * 128;
    if (m0 >= g_off[Ec]) return;
    int e = 0;
#pragma unroll
    for (int i = 1; i < Ec; i++) if (m0 >= g_off[i]) e = i;
    int n0 = blockIdx.x * 128;

    int tid = threadIdx.x, wid = tid >> 5, lane = tid & 31;
    int wm = wid & 3, wn = wid >> 2;
    int gi = lane >> 2, ti = lane & 3;

    // loader: 2 threads per row; each covers 16 halves (=16 fp32 for A)
    int r = tid >> 1;
    int ch = (tid & 1) * 16;   // half-col base

    int tok = g_tok[m0 + r];
    const float* xa = x + (size_t)(tok < 0 ? 0 : tok) * Dc + ch;
    size_t bb = ((size_t)e * HP2 + n0 + r) * Dc + ch;
    const __half* b1p = g_w1t + bb;
    const __half* b3p = g_w3t + bb;

    uint32_t smb = smem_u32(sm);
    uint32_t dstB1 = smb + (uint32_t)(F1_B1 + r * SAH + ch) * 2;
    uint32_t dstB3 = smb + (uint32_t)(F1_B3 + r * SAH + ch) * 2;
    __half* sAst = sm + (r * SAH + ch);
    const uint32_t STGB = (uint32_t)F1_STGH * 2;   // stage bytes

    float acc1[2][8][4], acc3[2][8][4];
#pragma unroll
    for (int mt = 0; mt < 2; mt++)
#pragma unroll
        for (int nt = 0; nt < 8; nt++)
#pragma unroll
            for (int j = 0; j < 4; j++) { acc1[mt][nt][j] = 0.f; acc3[mt][nt][j] = 0.f; }

    const int nc = Dc / KC;   // 32

    // ---- prologue: chunk 0 -> stage 0 ----
    {
        float4 a0 = make_float4(0,0,0,0), a1 = a0, a2 = a0, a3 = a0;
        if (tok >= 0) {
            a0 = *(const float4*)(xa);     a1 = *(const float4*)(xa + 4);
            a2 = *(const float4*)(xa + 8); a3 = *(const float4*)(xa + 12);
        }
        CP16(dstB1, b1p); CP16(dstB1 + 16, b1p + 8);
        CP16(dstB3, b3p); CP16(dstB3 + 16, b3p + 8);
        CP_COMMIT();
        __half2* s2 = (__half2*)sAst;
        s2[0] = __floats2half2_rn(a0.x, a0.y); s2[1] = __floats2half2_rn(a0.z, a0.w);
        s2[2] = __floats2half2_rn(a1.x, a1.y); s2[3] = __floats2half2_rn(a1.z, a1.w);
        s2[4] = __floats2half2_rn(a2.x, a2.y); s2[5] = __floats2half2_rn(a2.z, a2.w);
        s2[6] = __floats2half2_rn(a3.x, a3.y); s2[7] = __floats2half2_rn(a3.z, a3.w);
        CP_WAIT0();
        __syncthreads();
    }

    for (int c = 0; c < nc; ++c) {
        int cur = c & 1, nxt = cur ^ 1;
        bool pf = (c + 1 < nc);
        float4 a0, a1, a2, a3;
        if (pf) {
            int k0 = (c + 1) * KC;
            a0 = make_float4(0,0,0,0); a1 = a0; a2 = a0; a3 = a0;
            if (tok >= 0) {
                a0 = *(const float4*)(xa + k0);     a1 = *(const float4*)(xa + k0 + 4);
                a2 = *(const float4*)(xa + k0 + 8); a3 = *(const float4*)(xa + k0 + 12);
            }
            uint32_t so = nxt * STGB;
            CP16(dstB1 + so, b1p + k0); CP16(dstB1 + so + 16, b1p + k0 + 8);
            CP16(dstB3 + so, b3p + k0); CP16(dstB3 + so + 16, b3p + k0 + 8);
            CP_COMMIT();
        }
        // ---- compute chunk c from stage cur ----
        {
            const __half* sA  = sm + cur * F1_STGH + F1_A;
            const __half* sB1 = sm + cur * F1_STGH + F1_B1;
            const __half* sB3 = sm + cur * F1_STGH + F1_B3;
#pragma unroll
            for (int ks = 0; ks < 2; ks++) {
                int kb = ks * 16;
                uint32_t af[2][4];
#pragma unroll
                for (int mt = 0; mt < 2; mt++) {
                    int rb = wm * 32 + mt * 16;
                    af[mt][0] = U32S(sA, (rb + gi) * SAH + kb + 2 * ti);
                    af[mt][1] = U32S(sA, (rb + gi + 8) * SAH + kb + 2 * ti);
                    af[mt][2] = U32S(sA, (rb + gi) * SAH + kb + 8 + 2 * ti);
                    af[mt][3] = U32S(sA, (rb + gi + 8) * SAH + kb + 8 + 2 * ti);
                }
#pragma unroll
                for (int nt = 0; nt < 8; nt++) {
                    int nb = (wn * 64 + nt * 8 + gi) * SAH + kb + 2 * ti;
                    uint32_t bf1[2] = {U32S(sB1, nb), U32S(sB1, nb + 8)};
                    uint32_t bf3[2] = {U32S(sB3, nb), U32S(sB3, nb + 8)};
                    mma16(acc1[0][nt], af[0], bf1);
                    mma16(acc1[1][nt], af[1], bf1);
                    mma16(acc3[0][nt], af[0], bf3);
                    mma16(acc3[1][nt], af[1], bf3);
                }
            }
        }
        if (pf) {
            __half2* s2 = (__half2*)(sAst + nxt * F1_STGH);
            s2[0] = __floats2half2_rn(a0.x, a0.y); s2[1] = __floats2half2_rn(a0.z, a0.w);
            s2[2] = __floats2half2_rn(a1.x, a1.y); s2[3] = __floats2half2_rn(a1.z, a1.w);
            s2[4] = __floats2half2_rn(a2.x, a2.y); s2[5] = __floats2half2_rn(a2.z, a2.w);
            s2[6] = __floats2half2_rn(a3.x, a3.y); s2[7] = __floats2half2_rn(a3.z, a3.w);
        }
        CP_WAIT0();
        __syncthreads();
    }

    // ---- epilogue: silu(d1)*d3 -> g_h (fp16) ----
#pragma unroll
    for (int mt = 0; mt < 2; mt++) {
#pragma unroll
        for (int nt = 0; nt < 8; nt++) {
            int row = m0 + wm * 32 + mt * 16 + gi;
            int col = n0 + wn * 64 + nt * 8 + 2 * ti;
            const float* d1 = acc1[mt][nt];
            const float* d3 = acc3[mt][nt];
            float h0 = d1[0] / (1.0f + __expf(-d1[0])) * d3[0];
            float h1 = d1[1] / (1.0f + __expf(-d1[1])) * d3[1];
            float h2 = d1[2] / (1.0f + __expf(-d1[2])) * d3[2];
            float h3 = d1[3] / (1.0f + __expf(-d1[3])) * d3[3];
            *(__half2*)(g_h + (size_t)row * HP2 + col)       = __floats2half2_rn(h0, h1);
            *(__half2*)(g_h + (size_t)(row + 8) * HP2 + col) = __floats2half2_rn(h2, h3);
        }
    }
}

// ============ FFN2: y = gate * (h @ W2t), 128x128 tiles ============
#define F2_A     0
#define F2_B     (128 * SAH)
#define F2_STGH  (256 * SAH)
#define F2_SMEM  (2 * F2_STGH * 2)     // bytes = 40960

__global__ void __launch_bounds__(256, 1) k_ffn2() {
    extern __shared__ __half sm[];
    int m0 = blockIdx.y * 128;
    if (m0 >= g_off[Ec]) return;
    int e = 0;
#pragma unroll
    for (int i = 1; i < Ec; i++) if (m0 >= g_off[i]) e = i;
    int n0 = blockIdx.x * 128;

    int tid = threadIdx.x, wid = tid >> 5, lane = tid & 31;
    int wm = wid & 3, wn = wid >> 2;
    int gi = lane >> 2, ti = lane & 3;

    int r = tid >> 1;
    int ch = (tid & 1) * 16;

    const __half* ap = g_h + (size_t)(m0 + r) * HP2 + ch;
    const __half* bp = g_w2t + ((size_t)e * Dc + n0 + r) * HP2 + ch;

    uint32_t smb = smem_u32(sm);
    uint32_t dstA = smb + (uint32_t)(F2_A + r * SAH + ch) * 2;
    uint32_t dstB = smb + (uint32_t)(F2_B + r * SAH + ch) * 2;
    const uint32_t STGB = (uint32_t)F2_STGH * 2;

    float acc[2][8][4];
#pragma unroll
    for (int mt = 0; mt < 2; mt++)
#pragma unroll
        for (int nt = 0; nt < 8; nt++)
#pragma unroll
            for (int j = 0; j < 4; j++) acc[mt][nt][j] = 0.f;

    const int nc = HP2 / KC;   // 88

    // prologue
    CP16(dstA, ap); CP16(dstA + 16, ap + 8);
    CP16(dstB, bp); CP16(dstB + 16, bp + 8);
    CP_COMMIT();
    CP_WAIT0();
    __syncthreads();

    for (int c = 0; c < nc; ++c) {
        int cur = c & 1, nxt = cur ^ 1;
        if (c + 1 < nc) {
            int k0 = (c + 1) * KC;
            uint32_t so = nxt * STGB;
            CP16(dstA + so, ap + k0); CP16(dstA + so + 16, ap + k0 + 8);
            CP16(dstB + so, bp + k0); CP16(dstB + so + 16, bp + k0 + 8);
            CP_COMMIT();
        }
        const __half* sA = sm + cur * F2_STGH + F2_A;
        const __half* sB = sm + cur * F2_STGH + F2_B;
#pragma unroll
        for (int ks = 0; ks < 2; ks++) {
            int kb = ks * 16;
            uint32_t af[2][4];
#pragma unroll
            for (int mt = 0; mt < 2; mt++) {
                int rb = wm * 32 + mt * 16;
                af[mt][0] = U32S(sA, (rb + gi) * SAH + kb + 2 * ti);
                af[mt][1] = U32S(sA, (rb + gi + 8) * SAH + kb + 2 * ti);
                af[mt][2] = U32S(sA, (rb + gi) * SAH + kb + 8 + 2 * ti);
                af[mt][3] = U32S(sA, (rb + gi + 8) * SAH + kb + 8 + 2 * ti);
            }
#pragma unroll
            for (int nt = 0; nt < 8; nt++) {
                int nb = (wn * 64 + nt * 8 + gi) * SAH + kb + 2 * ti;
                uint32_t bf[2] = {U32S(sB, nb), U32S(sB, nb + 8)};
                mma16(acc[0][nt], af[0], bf);
                mma16(acc[1][nt], af[1], bf);
            }
        }
        CP_WAIT0();
        __syncthreads();
    }

    // epilogue: gate multiply -> g_y (fp32)
#pragma unroll
    for (int mt = 0; mt < 2; mt++) {
        int row = m0 + wm * 32 + mt * 16 + gi;
        float ga = g_gate[row];
        float gb = g_gate[row + 8];
#pragma unroll
        for (int nt = 0; nt < 8; nt++) {
            int col = n0 + wn * 64 + nt * 8 + 2 * ti;
            const float* d = acc[mt][nt];
            float2 o0, o1;
            o0.x = ga * d[0]; o0.y = ga * d[1];
            o1.x = gb * d[2]; o1.y = gb * d[3];
            *(float2*)(g_y + (size_t)row * Dc + col) = o0;
            *(float2*)(g_y + (size_t)(row + 8) * Dc + col) = o1;
        }
    }
}

// ---------------- combine ----------------
__global__ void k_combine(float* __restrict__ out) {
    int i = blockIdx.x * blockDim.x + threadIdx.x;
    int n = i >> 8;
    int c = (i & 255) * 4;
    int p0 = g_pos[2 * n], p1 = g_pos[2 * n + 1];
    float4 a = *(const float4*)&g_y[(size_t)p0 * Dc + c];
    float4 b = *(const float4*)&g_y[(size_t)p1 * Dc + c];
    float4 o;
    o.x = a.x + b.x; o.y = a.y + b.y; o.z = a.z + b.z; o.w = a.w + b.w;
    *(float4*)(out + (size_t)n * Dc + c) = o;
}

// ---------------- launch ----------------
extern "C" void kernel_launch(void* const* d_in, const int* in_sizes, int n_in,
                              void* d_out, int out_size) {
    const float* x  = (const float*)d_in[0];
    const float* Wr = (const float*)d_in[1];
    const float* W1 = (const float*)d_in[2];
    const float* W2 = (const float*)d_in[3];
    const float* W3 = (const float*)d_in[4];
    float* out = (float*)d_out;

    __half* w1t; cudaGetSymbolAddress((void**)&w1t, g_w1t);
    __half* w3t; cudaGetSymbolAddress((void**)&w3t, g_w3t);
    __half* w2t; cudaGetSymbolAddress((void**)&w2t, g_w2t);

    cudaFuncSetAttribute(k_ffn1, cudaFuncAttributeMaxDynamicSharedMemorySize, F1_SMEM);
    cudaFuncSetAttribute(k_ffn2, cudaFuncAttributeMaxDynamicSharedMemorySize, F2_SMEM);

    k_init<<<(MMAX + 255) / 256, 256>>>();

    dim3 tb(32, 8);
    // W1,W3: [E][Dc][Hc] -> [E][HP2][Dc]
    k_transpose<<<dim3(HP2 / 32, Dc / 32, Ec), tb>>>(W1, w1t, Dc, Hc, Dc, HP2);
    k_transpose<<<dim3(HP2 / 32, Dc / 32, Ec), tb>>>(W3, w3t, Dc, Hc, Dc, HP2);
    // W2: [E][Hc][Dc] -> [E][Dc][HP2]
    k_transpose<<<dim3(Dc / 32, HP2 / 32, Ec), tb>>>(W2, w2t, Hc, Dc, HP2, Dc);

    k_router<<<NT / 8, 256>>>(x, Wr);
    k_scan<<<1, 32>>>();
    k_scatter<<<NT / 256, 256>>>();

    k_ffn1<<<dim3(HP2 / 128, MMAX / 128), 256, F1_SMEM>>>(x);
    k_ffn2<<<dim3(Dc / 128, MMAX / 128), 256, F2_SMEM>>>();

    k_combine<<<(NT * (Dc / 4)) / 256, 256>>>(out);
}

// round 5
// speedup vs baseline: 4.5300x; 1.1618x over previous
#include <cuda_runtime.h>
#include <cuda_fp16.h>
#include <cstdint>

// ---------------- problem constants ----------------
#define Dc   1024
#define Ec   8
#define Hc   2730
#define HP2  2816            // H padded to 22*128
#define NT   8192
#define TMp  128             // per-expert row padding
#define MMAX (2*NT + Ec*TMp) // 17408
#define KCH  64              // K halves per pipeline chunk (4 x k16)

// smem strides (halves)
#define SA1  72              // A row stride (64 K + 8 pad)
#define SB1  136             // B row stride (128 N + 8 pad), rows = K

// FFN1 stage layout (halves): A[128][72], B1[64][136], B3[64][136]
#define F1_B1OFF 9216
#define F1_B3OFF 17920
#define F1_STGH  26624
#define F1_SMEM  (3 * F1_STGH * 2)    // 159744 B
// FFN2 stage layout: A[128][72], B[64][136]
#define F2_BOFF  9216
#define F2_STGH  17920
#define F2_SMEM  (3 * F2_STGH * 2)    // 107520 B

// ---------------- device scratch ----------------
__device__ int    g_cnt[Ec];
__device__ int    g_cur[Ec];
__device__ int    g_off[Ec + 1];
__device__ int    g_tok[MMAX];
__device__ float  g_gate[MMAX];
__device__ int    g_topi[NT * 2];
__device__ float  g_topv[NT * 2];
__device__ int    g_pos[NT * 2];
__device__ __half g_w1h[(size_t)Ec * Dc * HP2];   // W1 fp16 [E][Dc][HP2] (K-major rows, N contiguous)
__device__ __half g_w3h[(size_t)Ec * Dc * HP2];   // W3 fp16
__device__ __half g_w2h[(size_t)Ec * HP2 * Dc];   // W2 fp16 [E][HP2][Dc]
__device__ __half g_xh[(size_t)NT * Dc];          // x fp16
__device__ __half g_h[(size_t)MMAX * HP2];        // activations fp16
__device__ float  g_y[(size_t)MMAX * Dc];

// ---------------- helpers ----------------
__device__ __forceinline__ uint32_t smem_u32(const void* p) {
    uint32_t a;
    asm("{ .reg .u64 t; cvta.to.shared.u64 t, %1; cvt.u32.u64 %0, t; }" : "=r"(a) : "l"(p));
    return a;
}
#define CP16(dst, src) asm volatile("cp.async.cg.shared.global [%0], [%1], 16;" :: "r"(dst), "l"(src) : "memory")
#define CP_COMMIT()    asm volatile("cp.async.commit_group;" ::: "memory")
#define CP_WAIT0()     asm volatile("cp.async.wait_group 0;" ::: "memory")
#define CP_WAIT1()     asm volatile("cp.async.wait_group 1;" ::: "memory")

__device__ __forceinline__ void ldsm_x4(uint32_t* r, uint32_t a) {
    asm volatile("ldmatrix.sync.aligned.m8n8.x4.shared.b16 {%0,%1,%2,%3}, [%4];"
        : "=r"(r[0]), "=r"(r[1]), "=r"(r[2]), "=r"(r[3]) : "r"(a));
}
__device__ __forceinline__ void ldsm_x2t(uint32_t* r, uint32_t a) {
    asm volatile("ldmatrix.sync.aligned.m8n8.x2.trans.shared.b16 {%0,%1}, [%2];"
        : "=r"(r[0]), "=r"(r[1]) : "r"(a));
}
__device__ __forceinline__ void mma16(float* d, const uint32_t* a, const uint32_t* b) {
    asm volatile(
        "mma.sync.aligned.m16n8k16.row.col.f32.f16.f16.f32 "
        "{%0,%1,%2,%3}, {%4,%5,%6,%7}, {%8,%9}, {%0,%1,%2,%3};"
        : "+f"(d[0]), "+f"(d[1]), "+f"(d[2]), "+f"(d[3])
        : "r"(a[0]), "r"(a[1]), "r"(a[2]), "r"(a[3]), "r"(b[0]), "r"(b[1]));
}

// ---------------- init ----------------
__global__ void k_init() {
    int i = blockIdx.x * blockDim.x + threadIdx.x;
    if (i < Ec) { g_cnt[i] = 0; g_cur[i] = 0; }
    if (i < MMAX) { g_tok[i] = -1; g_gate[i] = 0.0f; }
}

// ---------------- fp16 converts (no transpose) ----------------
// W1/W3: [E*Dc][Hc] fp32 -> [E*Dc][HP2] fp16, pad cols with 0
__global__ void k_w13h(const float* __restrict__ in, __half* __restrict__ out) {
    int row = blockIdx.x;                       // 0 .. E*Dc-1
    const float* ip = in + (size_t)row * Hc;
    __half* op = out + (size_t)row * HP2;
    for (int j = threadIdx.x * 2; j < HP2; j += 512) {
        __half2 v = __floats2half2_rn(0.f, 0.f);
        if (j < Hc) { float2 f = *(const float2*)(ip + j); v = __floats2half2_rn(f.x, f.y); }
        *(__half2*)(op + j) = v;
    }
}
// W2: [E][Hc][Dc] fp32 -> [E][HP2][Dc] fp16, pad rows with 0
__global__ void k_w2h(const float* __restrict__ in, __half* __restrict__ out) {
    int row = blockIdx.x;                       // 0 .. E*HP2-1
    int e = row / HP2, hp = row % HP2;
    __half* op = out + (size_t)row * Dc;
    if (hp < Hc) {
        const float* ip = in + ((size_t)e * Hc + hp) * Dc;
        for (int j = threadIdx.x * 2; j < Dc; j += 512) {
            float2 f = *(const float2*)(ip + j);
            *(__half2*)(op + j) = __floats2half2_rn(f.x, f.y);
        }
    } else {
        for (int j = threadIdx.x * 2; j < Dc; j += 512)
            *(__half2*)(op + j) = __floats2half2_rn(0.f, 0.f);
    }
}
// x fp32 -> fp16
__global__ void k_xh(const float* __restrict__ x) {
    int i = blockIdx.x * blockDim.x + threadIdx.x;      // over NT*Dc/2
    float2 f = *(const float2*)(x + (size_t)i * 2);
    *(__half2*)(g_xh + (size_t)i * 2) = __floats2half2_rn(f.x, f.y);
}

// ---------------- router ----------------
__global__ void k_router(const float* __restrict__ x, const float* __restrict__ Wr) {
    int warp = threadIdx.x >> 5, lane = threadIdx.x & 31;
    int n = blockIdx.x * 8 + warp;
    if (n >= NT) return;
    const float* xr = x + (size_t)n * Dc;
    float acc[Ec];
#pragma unroll
    for (int e = 0; e < Ec; e++) acc[e] = 0.0f;
    for (int d0 = lane * 4; d0 < Dc; d0 += 128) {
        float4 xv = *(const float4*)(xr + d0);
        float xs[4] = {xv.x, xv.y, xv.z, xv.w};
#pragma unroll
        for (int j = 0; j < 4; j++) {
            float4 w0 = *(const float4*)(Wr + (d0 + j) * Ec);
            float4 w1 = *(const float4*)(Wr + (d0 + j) * Ec + 4);
            acc[0] += xs[j] * w0.x; acc[1] += xs[j] * w0.y;
            acc[2] += xs[j] * w0.z; acc[3] += xs[j] * w0.w;
            acc[4] += xs[j] * w1.x; acc[5] += xs[j] * w1.y;
            acc[6] += xs[j] * w1.z; acc[7] += xs[j] * w1.w;
        }
    }
#pragma unroll
    for (int e = 0; e < Ec; e++)
#pragma unroll
        for (int o = 16; o > 0; o >>= 1)
            acc[e] += __shfl_xor_sync(0xffffffffu, acc[e], o);
    if (lane == 0) {
        float mx = acc[0];
#pragma unroll
        for (int e = 1; e < Ec; e++) mx = fmaxf(mx, acc[e]);
        float p[Ec], s = 0.0f;
#pragma unroll
        for (int e = 0; e < Ec; e++) { p[e] = __expf(acc[e] - mx); s += p[e]; }
        float inv = 1.0f / s;
        int i1 = 0;
#pragma unroll
        for (int e = 1; e < Ec; e++) if (p[e] > p[i1]) i1 = e;
        int i2 = (i1 == 0) ? 1 : 0;
#pragma unroll
        for (int e = 0; e < Ec; e++) if (e != i1 && p[e] > p[i2]) i2 = e;
        g_topi[2 * n] = i1;     g_topv[2 * n] = p[i1] * inv;
        g_topi[2 * n + 1] = i2; g_topv[2 * n + 1] = p[i2] * inv;
        atomicAdd(&g_cnt[i1], 1);
        atomicAdd(&g_cnt[i2], 1);
    }
}

__global__ void k_scan() {
    if (threadIdx.x == 0 && blockIdx.x == 0) {
        int o = 0;
        for (int e = 0; e < Ec; e++) {
            g_off[e] = o;
            o += ((g_cnt[e] + TMp - 1) / TMp) * TMp;
        }
        g_off[Ec] = o;
    }
}

__global__ void k_scatter() {
    int n = blockIdx.x * blockDim.x + threadIdx.x;
    if (n >= NT) return;
#pragma unroll
    for (int k = 0; k < 2; k++) {
        int e = g_topi[2 * n + k];
        int pos = g_off[e] + atomicAdd(&g_cur[e], 1);
        g_tok[pos] = n;
        g_gate[pos] = g_topv[2 * n + k];
        g_pos[2 * n + k] = pos;
    }
}

// ============ FFN1: h = silu(X@W1) * (X@W3), 128x128 tiles ============
__global__ void __launch_bounds__(256) k_ffn1() {
    extern __shared__ __half sm[];
    int m0 = blockIdx.y * 128;
    if (m0 >= g_off[Ec]) return;
    int e = 0;
#pragma unroll
    for (int i = 1; i < Ec; i++) if (m0 >= g_off[i]) e = i;
    int n0 = blockIdx.x * 128;

    int tid = threadIdx.x, wid = tid >> 5, lane = tid & 31;
    int wm = wid & 3, wn = wid >> 2;
    int gi = lane >> 2, ti = lane & 3;
    uint32_t smb = smem_u32(sm);

    // ---- loader coords ----
    int rA = tid >> 1, chA = (tid & 1) * 32;            // A: 2 thr/row, 32 halves each
    int rB = tid >> 2, cnB = (tid & 3) * 32;            // B: 4 thr/row, 32 halves each
    int tok = g_tok[m0 + rA];
    const __half* srcA  = g_xh + (size_t)(tok < 0 ? 0 : tok) * Dc + chA;
    const __half* srcB1 = g_w1h + ((size_t)e * Dc + rB) * HP2 + n0 + cnB;
    const __half* srcB3 = g_w3h + ((size_t)e * Dc + rB) * HP2 + n0 + cnB;
    uint32_t dstA  = smb + (uint32_t)(rA * SA1 + chA) * 2;
    uint32_t dstB1 = smb + (uint32_t)(F1_B1OFF + rB * SB1 + cnB) * 2;
    uint32_t dstB3 = smb + (uint32_t)(F1_B3OFF + rB * SB1 + cnB) * 2;
    const uint32_t STGB = (uint32_t)F1_STGH * 2;

    auto issue = [&](int kc, int buf) {
        int k0 = kc * KCH;
        uint32_t so = buf * STGB;
        const __half* sA = srcA + k0;
        uint32_t dA = dstA + so;
        CP16(dA, sA); CP16(dA + 16, sA + 8); CP16(dA + 32, sA + 16); CP16(dA + 48, sA + 24);
        const __half* s1 = srcB1 + (size_t)k0 * HP2;
        uint32_t d1 = dstB1 + so;
        CP16(d1, s1); CP16(d1 + 16, s1 + 8); CP16(d1 + 32, s1 + 16); CP16(d1 + 48, s1 + 24);
        const __half* s3 = srcB3 + (size_t)k0 * HP2;
        uint32_t d3 = dstB3 + so;
        CP16(d3, s3); CP16(d3 + 16, s3 + 8); CP16(d3 + 32, s3 + 16); CP16(d3 + 48, s3 + 24);
    };

    // ---- fragment address bases ----
    int aRow = wm * 32 + (lane & 7) + 8 * ((lane >> 3) & 1);
    uint32_t aBase = smb + (uint32_t)(aRow * SA1 + 8 * (lane >> 4)) * 2;
    int bRowK = (lane & 7) + 8 * ((lane >> 3) & 1);
    uint32_t bBase = smb + (uint32_t)(F1_B1OFF + bRowK * SB1 + wn * 64) * 2;
    const uint32_t B3DELTA = (uint32_t)(F1_B3OFF - F1_B1OFF) * 2;   // 17408

    float acc1[2][8][4], acc3[2][8][4];
#pragma unroll
    for (int mt = 0; mt < 2; mt++)
#pragma unroll
        for (int nt = 0; nt < 8; nt++)
#pragma unroll
            for (int j = 0; j < 4; j++) { acc1[mt][nt][j] = 0.f; acc3[mt][nt][j] = 0.f; }

    const int nc = Dc / KCH;   // 16
    issue(0, 0); CP_COMMIT();
    issue(1, 1); CP_COMMIT();

    for (int c = 0; c < nc; ++c) {
        if (c + 1 < nc) CP_WAIT1(); else CP_WAIT0();
        __syncthreads();
        if (c + 2 < nc) { issue(c + 2, (c + 2) % 3); CP_COMMIT(); }
        uint32_t so = (uint32_t)(c % 3) * STGB;
        uint32_t aA = aBase + so;
        uint32_t bB = bBase + so;
#pragma unroll
        for (int ks = 0; ks < 4; ks++) {
            uint32_t af[2][4];
            ldsm_x4(af[0], aA + ks * 32);
            ldsm_x4(af[1], aA + 2304 + ks * 32);          // +16 rows * SA1 * 2
#pragma unroll
            for (int nt = 0; nt < 8; nt++) {
                uint32_t bo = bB + ks * 4352 + nt * 16;    // +16 K rows * SB1 * 2 per ks
                uint32_t bf1[2], bf3[2];
                ldsm_x2t(bf1, bo);
                ldsm_x2t(bf3, bo + B3DELTA);
                mma16(acc1[0][nt], af[0], bf1);
                mma16(acc1[1][nt], af[1], bf1);
                mma16(acc3[0][nt], af[0], bf3);
                mma16(acc3[1][nt], af[1], bf3);
            }
        }
    }

    // ---- epilogue: silu(d1)*d3 -> g_h (fp16) ----
#pragma unroll
    for (int mt = 0; mt < 2; mt++) {
#pragma unroll
        for (int nt = 0; nt < 8; nt++) {
            int row = m0 + wm * 32 + mt * 16 + gi;
            int col = n0 + wn * 64 + nt * 8 + 2 * ti;
            const float* d1 = acc1[mt][nt];
            const float* d3 = acc3[mt][nt];
            float h0 = d1[0] / (1.0f + __expf(-d1[0])) * d3[0];
            float h1 = d1[1] / (1.0f + __expf(-d1[1])) * d3[1];
            float h2 = d1[2] / (1.0f + __expf(-d1[2])) * d3[2];
            float h3 = d1[3] / (1.0f + __expf(-d1[3])) * d3[3];
            *(__half2*)(g_h + (size_t)row * HP2 + col)       = __floats2half2_rn(h0, h1);
            *(__half2*)(g_h + (size_t)(row + 8) * HP2 + col) = __floats2half2_rn(h2, h3);
        }
    }
}

// ============ FFN2: y = gate * (h @ W2), 128x128 tiles ============
__global__ void __launch_bounds__(256) k_ffn2() {
    extern __shared__ __half sm[];
    int m0 = blockIdx.y * 128;
    if (m0 >= g_off[Ec]) return;
    int e = 0;
#pragma unroll
    for (int i = 1; i < Ec; i++) if (m0 >= g_off[i]) e = i;
    int n0 = blockIdx.x * 128;

    int tid = threadIdx.x, wid = tid >> 5, lane = tid & 31;
    int wm = wid & 3, wn = wid >> 2;
    int gi = lane >> 2, ti = lane & 3;
    uint32_t smb = smem_u32(sm);

    int rA = tid >> 1, chA = (tid & 1) * 32;
    int rB = tid >> 2, cnB = (tid & 3) * 32;
    const __half* srcA = g_h + (size_t)(m0 + rA) * HP2 + chA;
    const __half* srcB = g_w2h + ((size_t)e * HP2 + rB) * Dc + n0 + cnB;
    uint32_t dstA = smb + (uint32_t)(rA * SA1 + chA) * 2;
    uint32_t dstB = smb + (uint32_t)(F2_BOFF + rB * SB1 + cnB) * 2;
    const uint32_t STGB = (uint32_t)F2_STGH * 2;

    auto issue = [&](int kc, int buf) {
        int k0 = kc * KCH;
        uint32_t so = buf * STGB;
        const __half* sA = srcA + k0;
        uint32_t dA = dstA + so;
        CP16(dA, sA); CP16(dA + 16, sA + 8); CP16(dA + 32, sA + 16); CP16(dA + 48, sA + 24);
        const __half* sB = srcB + (size_t)k0 * Dc;
        uint32_t dB = dstB + so;
        CP16(dB, sB); CP16(dB + 16, sB + 8); CP16(dB + 32, sB + 16); CP16(dB + 48, sB + 24);
    };

    int aRow = wm * 32 + (lane & 7) + 8 * ((lane >> 3) & 1);
    uint32_t aBase = smb + (uint32_t)(aRow * SA1 + 8 * (lane >> 4)) * 2;
    int bRowK = (lane & 7) + 8 * ((lane >> 3) & 1);
    uint32_t bBase = smb + (uint32_t)(F2_BOFF + bRowK * SB1 + wn * 64) * 2;

    float acc[2][8][4];
#pragma unroll
    for (int mt = 0; mt < 2; mt++)
#pragma unroll
        for (int nt = 0; nt < 8; nt++)
#pragma unroll
            for (int j = 0; j < 4; j++) acc[mt][nt][j] = 0.f;

    const int nc = HP2 / KCH;   // 44
    issue(0, 0); CP_COMMIT();
    issue(1, 1); CP_COMMIT();

    for (int c = 0; c < nc; ++c) {
        if (c + 1 < nc) CP_WAIT1(); else CP_WAIT0();
        __syncthreads();
        if (c + 2 < nc) { issue(c + 2, (c + 2) % 3); CP_COMMIT(); }
        uint32_t so = (uint32_t)(c % 3) * STGB;
        uint32_t aA = aBase + so;
        uint32_t bB = bBase + so;
#pragma unroll
        for (int ks = 0; ks < 4; ks++) {
            uint32_t af[2][4];
            ldsm_x4(af[0], aA + ks * 32);
            ldsm_x4(af[1], aA + 2304 + ks * 32);
#pragma unroll
            for (int nt = 0; nt < 8; nt++) {
                uint32_t bf[2];
                ldsm_x2t(bf, bB + ks * 4352 + nt * 16);
                mma16(acc[0][nt], af[0], bf);
                mma16(acc[1][nt], af[1], bf);
            }
        }
    }

    // epilogue: gate multiply -> g_y (fp32)
#pragma unroll
    for (int mt = 0; mt < 2; mt++) {
        int row = m0 + wm * 32 + mt * 16 + gi;
        float ga = g_gate[row];
        float gb = g_gate[row + 8];
#pragma unroll
        for (int nt = 0; nt < 8; nt++) {
            int col = n0 + wn * 64 + nt * 8 + 2 * ti;
            const float* d = acc[mt][nt];
            float2 o0, o1;
            o0.x = ga * d[0]; o0.y = ga * d[1];
            o1.x = gb * d[2]; o1.y = gb * d[3];
            *(float2*)(g_y + (size_t)row * Dc + col) = o0;
            *(float2*)(g_y + (size_t)(row + 8) * Dc + col) = o1;
        }
    }
}

// ---------------- combine ----------------
__global__ void k_combine(float* __restrict__ out) {
    int i = blockIdx.x * blockDim.x + threadIdx.x;
    int n = i >> 8;
    int c = (i & 255) * 4;
    int p0 = g_pos[2 * n], p1 = g_pos[2 * n + 1];
    float4 a = *(const float4*)&g_y[(size_t)p0 * Dc + c];
    float4 b = *(const float4*)&g_y[(size_t)p1 * Dc + c];
    float4 o;
    o.x = a.x + b.x; o.y = a.y + b.y; o.z = a.z + b.z; o.w = a.w + b.w;
    *(float4*)(out + (size_t)n * Dc + c) = o;
}

// ---------------- launch ----------------
extern "C" void kernel_launch(void* const* d_in, const int* in_sizes, int n_in,
                              void* d_out, int out_size) {
    const float* x  = (const float*)d_in[0];
    const float* Wr = (const float*)d_in[1];
    const float* W1 = (const float*)d_in[2];
    const float* W2 = (const float*)d_in[3];
    const float* W3 = (const float*)d_in[4];
    float* out = (float*)d_out;

    __half* w1h; cudaGetSymbolAddress((void**)&w1h, g_w1h);
    __half* w3h; cudaGetSymbolAddress((void**)&w3h, g_w3h);
    __half* w2h; cudaGetSymbolAddress((void**)&w2h, g_w2h);

    cudaFuncSetAttribute(k_ffn1, cudaFuncAttributeMaxDynamicSharedMemorySize, F1_SMEM);
    cudaFuncSetAttribute(k_ffn2, cudaFuncAttributeMaxDynamicSharedMemorySize, F2_SMEM);

    k_init<<<(MMAX + 255) / 256, 256>>>();

    k_w13h<<<Ec * Dc, 256>>>(W1, w1h);
    k_w13h<<<Ec * Dc, 256>>>(W3, w3h);
    k_w2h<<<Ec * HP2, 256>>>(W2, w2h);
    k_xh<<<(NT * Dc / 2) / 256, 256>>>(x);

    k_router<<<NT / 8, 256>>>(x, Wr);
    k_scan<<<1, 32>>>();
    k_scatter<<<NT / 256, 256>>>();

    k_ffn1<<<dim3(HP2 / 128, MMAX / 128), 256, F1_SMEM>>>();
    k_ffn2<<<dim3(Dc / 128, MMAX / 128), 256, F2_SMEM>>>();

    k_combine<<<(NT * (Dc / 4)) / 256, 256>>>(out);
}